// round 6
// baseline (speedup 1.0000x reference)
#include <cuda_runtime.h>
#include <math.h>
#include <stdint.h>

// Problem constants
#define B_ 1024
#define I_ 256
#define O_ 256
#define K_ 128

// Tiling
#define OT 32         // outputs per CTA (lane = o)
#define BT 256        // batches per CTA
#define NSEG 16       // i-segments (grid.z)
#define ISEG (I_ / NSEG)
#define NW 16         // warps per CTA (512 threads)
#define BPW (BT / NW) // 16 batches per warp
#define RS 129        // row stride (floats), odd -> gather bank (lane+l)%32 conflict-free
#define NBUF 3        // cp.async ring depth (issue distance 1 => safe with single barrier)

// Per-(b,i) packed activation data [i][b]:
//  .x = silu(tanh(x))  .y = 1-frac  .z = frac  .w = bitcast(l*4) byte offset into row
__device__ float4 g_pack[I_ * B_];
// Exclusive partial sums per i-segment (deterministic, no atomics on floats)
__device__ float g_part[NSEG][B_][O_];
// Arrival counters per (o-tile, b-group); reset to 0 by the reducing CTA each launch
__device__ int g_cnt[32];

__device__ __forceinline__ uint32_t saddr(const void* p) {
    return (uint32_t)__cvta_generic_to_shared(p);
}
#define CP_ASYNC_4(dst, src)  asm volatile("cp.async.ca.shared.global [%0], [%1], 4;"  :: "r"(dst), "l"(src))
#define CP_ASYNC_16(dst, src) asm volatile("cp.async.ca.shared.global [%0], [%1], 16;" :: "r"(dst), "l"(src))
#define CP_COMMIT()           asm volatile("cp.async.commit_group;")
#define CP_WAIT1()            asm volatile("cp.async.wait_group 1;")

__global__ __launch_bounds__(256) void prep_kernel(const float* __restrict__ x) {
    int idx = blockIdx.x * 256 + threadIdx.x;
    int b = idx / I_;
    int i = idx % I_;
    float xv = x[idx];
    float ax = fabsf(xv);
    float e  = __expf(-2.0f * ax);
    float r  = (1.0f - e) / (1.0f + e);
    float p  = copysignf(r, xv);                 // tanh(x) in [-1,1] => clip identity
    float sg = 1.0f / (1.0f + __expf(-p));
    float act = p * sg;                           // silu(p)
    float scaled = fminf(fmaxf((p + 1.0f) * 63.5f, 0.0f), 127.0f);
    int   l    = (int)scaled;                     // 0..127
    float frac = scaled - (float)l;
    g_pack[i * B_ + b] = make_float4(act, 1.0f - frac, frac, __int_as_float(l * 4));
}

// Dynamic smem layout (floats):
//   sC   [NBUF][OT*RS]   raw coefficient rows (+1 pad/row, zeroed once)
//   sPk  [NBUF][BT]      float4 packed per-(b,i) scalars
//   sW   [ISEG][OT]      base weights (whole segment)
//   sSc  [ISEG][OT]      spline scales (whole segment)
#define SC_F   (NBUF * OT * RS)          // 12384 floats
#define SPK_F  (NBUF * BT * 4)           // 3072 floats
#define SW_F   (ISEG * OT)               // 512
#define DYN_F  (SC_F + SPK_F + 2 * SW_F) // 16480 floats = 65920 B

__global__ __launch_bounds__(512, 3) void kan_main(
    const float* __restrict__ bw,     // [O, I]
    const float* __restrict__ coeff,  // [O, I, K]
    const float* __restrict__ scale,  // [O, I]
    const float* __restrict__ bias,   // [O]
    float* __restrict__ out)          // [B, O]
{
    extern __shared__ float dyn[];
    float*  sC  = dyn;
    float4* sPk = (float4*)(dyn + SC_F);
    float*  sW  = dyn + SC_F + SPK_F;
    float*  sSc = sW + SW_F;
    __shared__ int sLast;

    const int tid  = threadIdx.x;
    const int lane = tid & 31;
    const int warp = tid >> 5;
    const int o0 = blockIdx.x * OT;
    const int b0 = blockIdx.y * BT;
    const int i0 = blockIdx.z * ISEG;
    const int r0 = warp * 2;
    const int r1 = warp * 2 + 1;

    // One-time preload: base weights + scales for the whole segment
    for (int t = tid; t < ISEG * OT; t += 512) {
        int oo = t >> 4, ii = t & 15;
        sW [ii * OT + oo] = bw   [(size_t)(o0 + oo) * I_ + i0 + ii];
        sSc[ii * OT + oo] = scale[(size_t)(o0 + oo) * I_ + i0 + ii];
    }
    // Zero the per-row pads once (cp.async never writes them; read only when l=127, frac=0)
    if (tid < NBUF * OT) {
        int bf = tid >> 5, rr = tid & 31;
        sC[bf * (OT * RS) + rr * RS + K_] = 0.0f;
    }

    // Stage iteration for absolute input index i into ring buffer 'buf' (pure cp.async)
    auto stage = [&](int i, int buf) {
        const float* s0 = coeff + ((size_t)(o0 + r0) * I_ + i) * (size_t)K_;
        const float* s1 = coeff + ((size_t)(o0 + r1) * I_ + i) * (size_t)K_;
        uint32_t d0 = saddr(&sC[buf * (OT * RS) + r0 * RS + lane]);
        uint32_t d1 = saddr(&sC[buf * (OT * RS) + r1 * RS + lane]);
#pragma unroll
        for (int j = 0; j < 4; j++) {
            CP_ASYNC_4(d0 + j * 128u, s0 + lane + 32 * j);
            CP_ASYNC_4(d1 + j * 128u, s1 + lane + 32 * j);
        }
        if (tid < BT)
            CP_ASYNC_16(saddr(&sPk[buf * BT + tid]), &g_pack[(size_t)i * B_ + b0 + tid]);
    };

    stage(i0, 0);
    CP_COMMIT();

    float acc[BPW];
#pragma unroll
    for (int j = 0; j < BPW; j++) acc[j] = 0.0f;

    int cur = 0, nxt = 1;
    for (int ii = 0; ii < ISEG; ii++) {
        if (ii + 1 < ISEG) stage(i0 + ii + 1, nxt);
        CP_COMMIT();          // (possibly empty) group keeps wait-count consistent
        CP_WAIT1();           // group for 'cur' complete (own-thread); barrier covers all threads
        __syncthreads();

        const float w = sW [ii * OT + lane];
        const float s = sSc[ii * OT + lane];
        const char* rowb = (const char*)&sC[cur * (OT * RS) + lane * RS];
        const float4* pkp = &sPk[cur * BT + warp * BPW];
        // Hot loop per (b,i): LDS.128 bcast + 2 conflict-free LDS.32 + 4 FMA-pipe ops
#pragma unroll
        for (int bb = 0; bb < BPW; bb++) {
            float4 pk = pkp[bb];
            int off = __float_as_int(pk.w);
            float cl = *(const float*)(rowb + off);
            float cr = *(const float*)(rowb + off + 4);
            float t1 = fmaf(pk.z, cr, pk.y * cl);   // (1-f)cl + f*cr
            acc[bb] = fmaf(s, t1, acc[bb]);         // * spline_scale
            acc[bb] = fmaf(pk.x, w, acc[bb]);       // + silu * base_weight
        }

        cur = nxt; nxt = (nxt == NBUF - 1) ? 0 : nxt + 1;
    }

    // Write exclusive partial slice (coalesced 128B rows)
#pragma unroll
    for (int bb = 0; bb < BPW; bb++)
        g_part[blockIdx.z][b0 + warp * BPW + bb][o0 + lane] = acc[bb];

    // Last-arriving CTA per (o-tile, b-group) reduces the NSEG partials (fixed order => deterministic)
    __threadfence();
    __syncthreads();
    if (tid == 0) {
        int old = atomicAdd(&g_cnt[blockIdx.x * 4 + blockIdx.y], 1);
        sLast = (old == NSEG - 1);
    }
    __syncthreads();
    if (sLast) {
#pragma unroll
        for (int j = 0; j < (BT * OT) / 512; j++) {
            int e  = tid + 512 * j;
            int bl = e >> 5;
            int oo = e & 31;
            float sum = bias[o0 + oo];
#pragma unroll
            for (int sg = 0; sg < NSEG; sg++)
                sum += g_part[sg][b0 + bl][o0 + oo];
            out[(size_t)(b0 + bl) * O_ + o0 + oo] = sum;
        }
        if (tid == 0) g_cnt[blockIdx.x * 4 + blockIdx.y] = 0;  // re-arm for next launch
    }
}

extern "C" void kernel_launch(void* const* d_in, const int* in_sizes, int n_in,
                              void* d_out, int out_size) {
    const float* x     = (const float*)d_in[0];
    const float* bw    = (const float*)d_in[1];
    const float* coeff = (const float*)d_in[2];
    const float* scale = (const float*)d_in[3];
    const float* bias  = (const float*)d_in[4];
    float* out = (float*)d_out;

    cudaFuncSetAttribute(kan_main, cudaFuncAttributeMaxDynamicSharedMemorySize, DYN_F * 4);

    prep_kernel<<<(B_ * I_) / 256, 256>>>(x);

    dim3 grid(O_ / OT, B_ / BT, NSEG);  // 8 x 4 x 16 = 512 CTAs
    kan_main<<<grid, 512, DYN_F * 4>>>(bw, coeff, scale, bias, out);
}